// round 14
// baseline (speedup 1.0000x reference)
#include <cuda_runtime.h>

#define NN 100000
#define EE 1600000
#define CAP 64   // max in-degree bucket capacity (Poisson(16): P(exceed) ~ 1e-19)
#define FULLM 0xffffffffu

// ---------------- scratch ---------------------------------------------------
__device__ int    g_cnt[NN];           // in-degree
__device__ int    g_slot[CAP * NN];    // src ids: slot[j*NN + dst], j < cnt[dst]
__device__ int    g_hist[CAP + 1];     // degree histogram
__device__ int    g_perm[NN];          // nodes sorted by degree
__device__ float4 g_bufA4[NN * 4];     // ping (max padded C = 16)
__device__ float4 g_bufB4[NN * 4];     // pong
__device__ float  g_stats[192];        // 3 layers x (32 sum + 32 sumsq)

// ---------------- bucket fill: one pass, column-major slots ------------------
__global__ void k_fill(const int* __restrict__ ei) {
    int e = blockIdx.x * blockDim.x + threadIdx.x;
    if (e >= EE) return;
    int s = ei[e];
    int d = ei[EE + e];
    int pos = atomicAdd(&g_cnt[d], 1);
    if (pos < CAP) g_slot[pos * NN + d] = s;
}

// ---------------- degree counting sort ---------------------------------------
__global__ void k_hist() {
    int n = blockIdx.x * blockDim.x + threadIdx.x;
    if (n >= NN) return;
    atomicAdd(&g_hist[min(g_cnt[n], CAP)], 1);
}
__global__ void k_hscan() {      // 1 block, exclusive scan of 65 bins
    __shared__ int s[CAP + 1];
    int t = threadIdx.x;
    if (t <= CAP) s[t] = g_hist[t];
    __syncthreads();
    if (t == 0) {
        int run = 0;
        for (int i = 0; i <= CAP; i++) { int v = s[i]; s[i] = run; run += v; }
    }
    __syncthreads();
    if (t <= CAP) g_hist[t] = s[t];  // reuse as cursors
}
__global__ void k_perm() {
    int n = blockIdx.x * blockDim.x + threadIdx.x;
    if (n >= NN) return;
    int d = min(g_cnt[n], CAP);
    int pos = atomicAdd(&g_hist[d], 1);
    g_perm[pos] = n;
}

// ---------------- fused layer (thread-per-node via degree-sorted perm) -------
template <int CI, int CO, int CPI, int CPO, bool LAST, bool HAS_BN,
          int SIN, int SOUT>
__global__ void node_kernel(const float4* __restrict__ x4,
                            const float* __restrict__ wl,
                            const float* __restrict__ bl,
                            const float* __restrict__ wr,
                            const float* __restrict__ bn_g,
                            const float* __restrict__ bn_b,
                            float* __restrict__ y) {
    constexpr int V = CPI / 4;
    constexpr int W = CPO / 4;
    __shared__ float s_wl[CO * CI];
    __shared__ float s_wr[CO * CI];
    __shared__ float s_bias[CO];
    __shared__ float s_sc[CI], s_sh[CI];
    __shared__ float s_sum[CO];
    __shared__ float s_sq[CO];

    if (HAS_BN) {
        if (threadIdx.x < CI) {
            int c = threadIdx.x;
            float m  = g_stats[SIN + c] * (1.0f / NN);
            float v  = g_stats[SIN + 32 + c] * (1.0f / NN) - m * m;
            float sc = bn_g[c] * rsqrtf(v + 1e-5f);
            s_sc[c] = sc;
            s_sh[c] = bn_b[c] - m * sc;
        }
        __syncthreads();
    }
    for (int i = threadIdx.x; i < CO * CI; i += blockDim.x) {
        float sc = HAS_BN ? s_sc[i % CI] : 1.0f;
        s_wl[i] = wl[i] * sc;
        s_wr[i] = wr[i] * sc;
    }
    if (threadIdx.x < CO) {
        int co = threadIdx.x;
        float b = bl[co];
        if (HAS_BN) {
#pragma unroll
            for (int i = 0; i < CI; i++)
                b += s_sh[i] * (wl[co * CI + i] + wr[co * CI + i]);
        }
        s_bias[co] = b;
        if (!LAST) { s_sum[co] = 0.0f; s_sq[co] = 0.0f; }
    }
    __syncthreads();

    int tix = blockIdx.x * blockDim.x + threadIdx.x;
    bool act = (tix < NN);
    int n = act ? g_perm[tix] : 0;

    float out[CO];
#pragma unroll
    for (int c = 0; c < CO; c++) out[c] = 0.0f;

    if (act) {
        float4 xv4[V];
        const float4* xr = x4 + (size_t)n * V;
#pragma unroll
        for (int v = 0; v < V; v++) xv4[v] = xr[v];

        float4 acc[V];
#pragma unroll
        for (int v = 0; v < V; v++) acc[v] = make_float4(0.f, 0.f, 0.f, 0.f);

        int deg = min(g_cnt[n], CAP);
        int j = 0;
        for (; j + 1 < deg; j += 2) {
            int s0 = g_slot[j * NN + n];
            int s1 = g_slot[(j + 1) * NN + n];
            const float4* r0 = x4 + (size_t)s0 * V;
            const float4* r1 = x4 + (size_t)s1 * V;
            float4 a0[V], a1[V];
#pragma unroll
            for (int v = 0; v < V; v++) { a0[v] = r0[v]; a1[v] = r1[v]; }
#pragma unroll
            for (int v = 0; v < V; v++) {
                acc[v].x += a0[v].x + a1[v].x;
                acc[v].y += a0[v].y + a1[v].y;
                acc[v].z += a0[v].z + a1[v].z;
                acc[v].w += a0[v].w + a1[v].w;
            }
        }
        if (j < deg) {
            int s0 = g_slot[j * NN + n];
            const float4* r0 = x4 + (size_t)s0 * V;
#pragma unroll
            for (int v = 0; v < V; v++) {
                float4 a0 = r0[v];
                acc[v].x += a0.x; acc[v].y += a0.y;
                acc[v].z += a0.z; acc[v].w += a0.w;
            }
        }

        float cinv = 1.0f / (float)max(deg, 1);
        float av[CI], xv[CI];
        const float* ap = reinterpret_cast<const float*>(acc);
        const float* xp = reinterpret_cast<const float*>(xv4);
#pragma unroll
        for (int i = 0; i < CI; i++) { av[i] = ap[i] * cinv; xv[i] = xp[i]; }

        float ss = 0.0f;
#pragma unroll
        for (int co = 0; co < CO; co++) {
            float t = s_bias[co];
#pragma unroll
            for (int i = 0; i < CI; i++) {
                t = fmaf(av[i], s_wl[co * CI + i], t);
                t = fmaf(xv[i], s_wr[co * CI + i], t);
            }
            out[co] = t;
            ss += t * t;
        }
        float inv = 1.0f / fmaxf(sqrtf(ss), 1e-12f);
#pragma unroll
        for (int co = 0; co < CO; co++)
            out[co] = fmaxf(out[co] * inv, 0.0f);   // L2 norm then relu

        float4* yr4 = reinterpret_cast<float4*>(y) + (size_t)n * W;
#pragma unroll
        for (int w = 0; w < W; w++) {
            float4 o;
            o.x = (4 * w + 0 < CO) ? out[4 * w + 0 < CO ? 4 * w + 0 : 0] : 0.0f;
            o.y = (4 * w + 1 < CO) ? out[4 * w + 1 < CO ? 4 * w + 1 : 0] : 0.0f;
            o.z = (4 * w + 2 < CO) ? out[4 * w + 2 < CO ? 4 * w + 2 : 0] : 0.0f;
            o.w = (4 * w + 3 < CO) ? out[4 * w + 3 < CO ? 4 * w + 3 : 0] : 0.0f;
            yr4[w] = o;
        }
    }

    if (!LAST) {
#pragma unroll
        for (int c = 0; c < CO; c++) {
            float v = out[c];
            float q = v * v;
#pragma unroll
            for (int off = 16; off; off >>= 1) {
                v += __shfl_xor_sync(FULLM, v, off);
                q += __shfl_xor_sync(FULLM, q, off);
            }
            if ((threadIdx.x & 31) == 0) {
                atomicAdd(&s_sum[c], v);
                atomicAdd(&s_sq[c], q);
            }
        }
        __syncthreads();
        if (threadIdx.x < CO) {
            atomicAdd(&g_stats[SOUT + threadIdx.x], s_sum[threadIdx.x]);
            atomicAdd(&g_stats[SOUT + 32 + threadIdx.x], s_sq[threadIdx.x]);
        }
    }
}

// ---------------- L4 kernel: 2 threads per node (edge-split, perm-sorted) ----
__global__ void l4_kernel(const float4* __restrict__ x4,
                          const float* __restrict__ wl,
                          const float* __restrict__ bl,
                          const float* __restrict__ wr,
                          const float* __restrict__ bn_g,
                          const float* __restrict__ bn_b,
                          float* __restrict__ y) {
    constexpr int CI = 16, CO = 32, V = 4, WS = CI + 1;
    __shared__ float s_wl[CO * WS];
    __shared__ float s_wr[CO * WS];
    __shared__ float s_bias[CO];
    __shared__ float s_sc[CI], s_sh[CI];

    if (threadIdx.x < CI) {
        int c = threadIdx.x;
        float m  = g_stats[128 + c] * (1.0f / NN);
        float v  = g_stats[128 + 32 + c] * (1.0f / NN) - m * m;
        float sc = bn_g[c] * rsqrtf(v + 1e-5f);
        s_sc[c] = sc;
        s_sh[c] = bn_b[c] - m * sc;
    }
    __syncthreads();
    for (int i = threadIdx.x; i < CO * CI; i += blockDim.x) {
        int co = i / CI, ci = i % CI;
        float sc = s_sc[ci];
        s_wl[co * WS + ci] = wl[i] * sc;
        s_wr[co * WS + ci] = wr[i] * sc;
    }
    if (threadIdx.x < CO) {
        int co = threadIdx.x;
        float b = bl[co];
#pragma unroll
        for (int i = 0; i < CI; i++)
            b += s_sh[i] * (wl[co * CI + i] + wr[co * CI + i]);
        s_bias[co] = b;
    }
    __syncthreads();

    int t = blockIdx.x * blockDim.x + threadIdx.x;
    int ti = t >> 1;                 // node slot in perm order
    int p = t & 1;                   // half (edge parity / channel half)
    bool act = (ti < NN);
    int n = act ? g_perm[ti] : 0;

    float4 xc0 = make_float4(0.f, 0.f, 0.f, 0.f);
    float4 xc1 = make_float4(0.f, 0.f, 0.f, 0.f);
    int deg = 0;
    if (act) {
        deg = min(g_cnt[n], CAP);
        xc0 = x4[(size_t)n * V + 2 * p + 0];
        xc1 = x4[(size_t)n * V + 2 * p + 1];
    }

    float4 acc[V];
#pragma unroll
    for (int v = 0; v < V; v++) acc[v] = make_float4(0.f, 0.f, 0.f, 0.f);
    for (int j = p; j < deg; j += 2) {
        int s0 = g_slot[j * NN + n];
        const float4* r0 = x4 + (size_t)s0 * V;
        float4 a0 = r0[0], a1 = r0[1], a2 = r0[2], a3 = r0[3];
        acc[0].x += a0.x; acc[0].y += a0.y; acc[0].z += a0.z; acc[0].w += a0.w;
        acc[1].x += a1.x; acc[1].y += a1.y; acc[1].z += a1.z; acc[1].w += a1.w;
        acc[2].x += a2.x; acc[2].y += a2.y; acc[2].z += a2.z; acc[2].w += a2.w;
        acc[3].x += a3.x; acc[3].y += a3.y; acc[3].z += a3.z; acc[3].w += a3.w;
    }

#pragma unroll
    for (int v = 0; v < V; v++) {
        acc[v].x += __shfl_xor_sync(FULLM, acc[v].x, 1);
        acc[v].y += __shfl_xor_sync(FULLM, acc[v].y, 1);
        acc[v].z += __shfl_xor_sync(FULLM, acc[v].z, 1);
        acc[v].w += __shfl_xor_sync(FULLM, acc[v].w, 1);
    }
    float xv[CI];
    {
        float oth[8];
        oth[0] = __shfl_xor_sync(FULLM, xc0.x, 1);
        oth[1] = __shfl_xor_sync(FULLM, xc0.y, 1);
        oth[2] = __shfl_xor_sync(FULLM, xc0.z, 1);
        oth[3] = __shfl_xor_sync(FULLM, xc0.w, 1);
        oth[4] = __shfl_xor_sync(FULLM, xc1.x, 1);
        oth[5] = __shfl_xor_sync(FULLM, xc1.y, 1);
        oth[6] = __shfl_xor_sync(FULLM, xc1.z, 1);
        oth[7] = __shfl_xor_sync(FULLM, xc1.w, 1);
        int mine = 8 * p, theirs = 8 * (1 - p);
        xv[mine + 0] = xc0.x; xv[mine + 1] = xc0.y;
        xv[mine + 2] = xc0.z; xv[mine + 3] = xc0.w;
        xv[mine + 4] = xc1.x; xv[mine + 5] = xc1.y;
        xv[mine + 6] = xc1.z; xv[mine + 7] = xc1.w;
#pragma unroll
        for (int k = 0; k < 8; k++) xv[theirs + k] = oth[k];
    }

    float cinv = 1.0f / (float)max(deg, 1);
    float av[CI];
    {
        const float* ap = reinterpret_cast<const float*>(acc);
#pragma unroll
        for (int i = 0; i < CI; i++) av[i] = ap[i] * cinv;
    }

    float outl[16];
    float ss = 0.0f;
#pragma unroll
    for (int k = 0; k < 16; k++) {
        int c = 16 * p + k;
        float tt = s_bias[c];
#pragma unroll
        for (int i = 0; i < CI; i++) {
            tt = fmaf(av[i], s_wl[c * WS + i], tt);
            tt = fmaf(xv[i], s_wr[c * WS + i], tt);
        }
        outl[k] = tt;
        ss += tt * tt;
    }
    ss += __shfl_xor_sync(FULLM, ss, 1);
    float inv = 1.0f / fmaxf(sqrtf(ss), 1e-12f);

    if (act) {
        float4* yr = reinterpret_cast<float4*>(y) + (size_t)n * 8 + 4 * p;
#pragma unroll
        for (int w = 0; w < 4; w++) {
            float4 o;
            o.x = fmaxf(outl[4 * w + 0] * inv, 0.0f);
            o.y = fmaxf(outl[4 * w + 1] * inv, 0.0f);
            o.z = fmaxf(outl[4 * w + 2] * inv, 0.0f);
            o.w = fmaxf(outl[4 * w + 3] * inv, 0.0f);
            yr[w] = o;
        }
    }
}

// ---------------- launch ----------------------------------------------------
extern "C" void kernel_launch(void* const* d_in, const int* in_sizes, int n_in,
                              void* d_out, int out_size) {
    const float* x   = (const float*)d_in[0];
    const int*   ei  = (const int*)d_in[1];     // int32 edge_index (JAX x64 off)
    const float* w1l = (const float*)d_in[2];
    const float* b1l = (const float*)d_in[3];
    const float* w1r = (const float*)d_in[4];
    const float* w2l = (const float*)d_in[5];
    const float* b2l = (const float*)d_in[6];
    const float* w2r = (const float*)d_in[7];
    const float* w3l = (const float*)d_in[8];
    const float* b3l = (const float*)d_in[9];
    const float* w3r = (const float*)d_in[10];
    const float* w4l = (const float*)d_in[11];
    const float* b4l = (const float*)d_in[12];
    const float* w4r = (const float*)d_in[13];
    const float* g1  = (const float*)d_in[14];
    const float* be1 = (const float*)d_in[15];
    const float* g2  = (const float*)d_in[16];
    const float* be2 = (const float*)d_in[17];
    const float* g3  = (const float*)d_in[18];
    const float* be3 = (const float*)d_in[19];
    float* out = (float*)d_out;

    void *p_cnt, *p_hist, *p_stats, *p_bufA, *p_bufB;
    cudaGetSymbolAddress(&p_cnt, g_cnt);
    cudaGetSymbolAddress(&p_hist, g_hist);
    cudaGetSymbolAddress(&p_stats, g_stats);
    cudaGetSymbolAddress(&p_bufA, g_bufA4);
    cudaGetSymbolAddress(&p_bufB, g_bufB4);
    float* bufA = (float*)p_bufA;
    float* bufB = (float*)p_bufB;

    const int TB = 256;
    const int gridE  = (EE + TB - 1) / TB;
    const int gridN  = (NN + TB - 1) / TB;
    const int gridN2 = (2 * NN + TB - 1) / TB;

    // bucket build + degree counting sort
    cudaMemsetAsync(p_cnt, 0, NN * sizeof(int));
    cudaMemsetAsync(p_hist, 0, (CAP + 1) * sizeof(int));
    cudaMemsetAsync(p_stats, 0, 192 * sizeof(float));
    k_fill<<<gridE, TB>>>(ei);
    k_hist<<<gridN, TB>>>();
    k_hscan<<<1, 128>>>();
    k_perm<<<gridN, TB>>>();

    // L1: 4 -> 6 (pad 8), no input BN
    node_kernel<4, 6, 4, 8, false, false, 0, 0>
        <<<gridN, TB>>>((const float4*)x, w1l, b1l, w1r, nullptr, nullptr, bufA);

    // L2: 6 (pad 8) -> 8, BN1 folded
    node_kernel<6, 8, 8, 8, false, true, 0, 64>
        <<<gridN, TB>>>((const float4*)bufA, w2l, b2l, w2r, g1, be1, bufB);

    // L3: 8 -> 16, BN2 folded
    node_kernel<8, 16, 8, 16, false, true, 64, 128>
        <<<gridN, TB>>>((const float4*)bufB, w3l, b3l, w3r, g2, be2, bufA);

    // L4: 16 -> 32, BN3 folded, 2 threads/node edge-split, straight to d_out
    l4_kernel<<<gridN2, TB>>>((const float4*)bufA, w4l, b4l, w4r, g3, be3, out);
}

// round 15
// speedup vs baseline: 1.4051x; 1.4051x over previous
#include <cuda_runtime.h>

#define NN 100000
#define EE 1600000
#define CAP 64   // max in-degree bucket capacity (Poisson(16): P(exceed) ~ 1e-19)
#define FULLM 0xffffffffu

// ---------------- scratch ---------------------------------------------------
__device__ int    g_cnt[NN];           // in-degree
__device__ int    g_slot[CAP * NN];    // src ids: slot[j*NN + dst], j < cnt[dst]
__device__ float4 g_bufA4[NN * 4];     // ping (max padded C = 16)
__device__ float4 g_bufB4[NN * 4];     // pong
__device__ float  g_stats[192];        // 3 layers x (32 sum + 32 sumsq)

// ---------------- bucket fill: one pass, column-major slots ------------------
__global__ void k_fill(const int* __restrict__ ei) {
    int e = blockIdx.x * blockDim.x + threadIdx.x;
    if (e >= EE) return;
    int s = ei[e];
    int d = ei[EE + e];
    int pos = atomicAdd(&g_cnt[d], 1);
    if (pos < CAP) g_slot[pos * NN + d] = s;
}

// ---------------- L1 kernel (thread-per-node; V=1) ---------------------------
__global__ void l1_kernel(const float4* __restrict__ x4,
                          const float* __restrict__ wl,
                          const float* __restrict__ bl,
                          const float* __restrict__ wr,
                          float* __restrict__ y) {
    constexpr int CI = 4, CO = 6;
    __shared__ float s_wl[CO * CI];
    __shared__ float s_wr[CO * CI];
    __shared__ float s_bias[CO];
    __shared__ float s_sum[CO];
    __shared__ float s_sq[CO];
    for (int i = threadIdx.x; i < CO * CI; i += blockDim.x) {
        s_wl[i] = wl[i];
        s_wr[i] = wr[i];
    }
    if (threadIdx.x < CO) {
        s_bias[threadIdx.x] = bl[threadIdx.x];
        s_sum[threadIdx.x] = 0.0f;
        s_sq[threadIdx.x] = 0.0f;
    }
    __syncthreads();

    int n = blockIdx.x * blockDim.x + threadIdx.x;
    bool act = (n < NN);

    float out[CO];
#pragma unroll
    for (int c = 0; c < CO; c++) out[c] = 0.0f;

    if (act) {
        float4 xv4 = x4[n];
        float4 acc = make_float4(0.f, 0.f, 0.f, 0.f);
        int deg = min(g_cnt[n], CAP);
        int j = 0;
        for (; j + 1 < deg; j += 2) {
            int s0 = g_slot[j * NN + n];
            int s1 = g_slot[(j + 1) * NN + n];
            float4 a0 = x4[s0];
            float4 a1 = x4[s1];
            acc.x += a0.x + a1.x; acc.y += a0.y + a1.y;
            acc.z += a0.z + a1.z; acc.w += a0.w + a1.w;
        }
        if (j < deg) {
            int s0 = g_slot[j * NN + n];
            float4 a0 = x4[s0];
            acc.x += a0.x; acc.y += a0.y; acc.z += a0.z; acc.w += a0.w;
        }
        float cinv = 1.0f / (float)max(deg, 1);
        float av[CI] = { acc.x * cinv, acc.y * cinv, acc.z * cinv, acc.w * cinv };
        float xv[CI] = { xv4.x, xv4.y, xv4.z, xv4.w };

        float ss = 0.0f;
#pragma unroll
        for (int co = 0; co < CO; co++) {
            float t = s_bias[co];
#pragma unroll
            for (int i = 0; i < CI; i++) {
                t = fmaf(av[i], s_wl[co * CI + i], t);
                t = fmaf(xv[i], s_wr[co * CI + i], t);
            }
            out[co] = t;
            ss += t * t;
        }
        float inv = 1.0f / fmaxf(sqrtf(ss), 1e-12f);
#pragma unroll
        for (int co = 0; co < CO; co++)
            out[co] = fmaxf(out[co] * inv, 0.0f);

        float4* yr4 = reinterpret_cast<float4*>(y) + (size_t)n * 2;
        yr4[0] = make_float4(out[0], out[1], out[2], out[3]);
        yr4[1] = make_float4(out[4], out[5], 0.0f, 0.0f);
    }

#pragma unroll
    for (int c = 0; c < CO; c++) {
        float v = out[c];
        float q = v * v;
#pragma unroll
        for (int off = 16; off; off >>= 1) {
            v += __shfl_xor_sync(FULLM, v, off);
            q += __shfl_xor_sync(FULLM, q, off);
        }
        if ((threadIdx.x & 31) == 0) {
            atomicAdd(&s_sum[c], v);
            atomicAdd(&s_sq[c], q);
        }
    }
    __syncthreads();
    if (threadIdx.x < CO) {
        atomicAdd(&g_stats[0 + threadIdx.x], s_sum[threadIdx.x]);
        atomicAdd(&g_stats[32 + threadIdx.x], s_sq[threadIdx.x]);
    }
}

// ---------------- split layer: 2 threads/node, V=2 (L2, L3), reg-capped ------
template <int CI, int CO, int SIN, int SOUT>
__global__ __launch_bounds__(256, 5)
void split2_kernel(const float4* __restrict__ x4,
                   const float* __restrict__ wl,
                   const float* __restrict__ bl,
                   const float* __restrict__ wr,
                   const float* __restrict__ bn_g,
                   const float* __restrict__ bn_b,
                   float* __restrict__ y) {
    constexpr int CPI = 8, V = 2;
    constexpr int CPO = CO;
    constexpr int NCH = CO / 2;
    constexpr int WS  = CI + 1;
    __shared__ float s_wl[CO * WS];
    __shared__ float s_wr[CO * WS];
    __shared__ float s_bias[CO];
    __shared__ float s_sc[CI], s_sh[CI];
    __shared__ float s_sum[CO];
    __shared__ float s_sq[CO];

    if (threadIdx.x < CI) {
        int c = threadIdx.x;
        float m  = g_stats[SIN + c] * (1.0f / NN);
        float v  = g_stats[SIN + 32 + c] * (1.0f / NN) - m * m;
        float sc = bn_g[c] * rsqrtf(v + 1e-5f);
        s_sc[c] = sc;
        s_sh[c] = bn_b[c] - m * sc;
    }
    __syncthreads();
    for (int i = threadIdx.x; i < CO * CI; i += blockDim.x) {
        int co = i / CI, ci = i % CI;
        float sc = s_sc[ci];
        s_wl[co * WS + ci] = wl[i] * sc;
        s_wr[co * WS + ci] = wr[i] * sc;
    }
    if (threadIdx.x < CO) {
        int co = threadIdx.x;
        float b = bl[co];
#pragma unroll
        for (int i = 0; i < CI; i++)
            b += s_sh[i] * (wl[co * CI + i] + wr[co * CI + i]);
        s_bias[co] = b;
        s_sum[co] = 0.0f;
        s_sq[co] = 0.0f;
    }
    __syncthreads();

    int t = blockIdx.x * blockDim.x + threadIdx.x;
    int n = t >> 1;
    int p = t & 1;
    bool act = (n < NN);

    float4 xc = make_float4(0.f, 0.f, 0.f, 0.f);
    int deg = 0;
    if (act) {
        deg = min(g_cnt[n], CAP);
        xc = x4[(size_t)n * V + p];
    }

    float4 acc0 = make_float4(0.f, 0.f, 0.f, 0.f);
    float4 acc1 = make_float4(0.f, 0.f, 0.f, 0.f);
    for (int j = p; j < deg; j += 2) {
        int s0 = g_slot[j * NN + n];
        const float4* r0 = x4 + (size_t)s0 * V;
        float4 a0 = r0[0], a1 = r0[1];
        acc0.x += a0.x; acc0.y += a0.y; acc0.z += a0.z; acc0.w += a0.w;
        acc1.x += a1.x; acc1.y += a1.y; acc1.z += a1.z; acc1.w += a1.w;
    }

    acc0.x += __shfl_xor_sync(FULLM, acc0.x, 1);
    acc0.y += __shfl_xor_sync(FULLM, acc0.y, 1);
    acc0.z += __shfl_xor_sync(FULLM, acc0.z, 1);
    acc0.w += __shfl_xor_sync(FULLM, acc0.w, 1);
    acc1.x += __shfl_xor_sync(FULLM, acc1.x, 1);
    acc1.y += __shfl_xor_sync(FULLM, acc1.y, 1);
    acc1.z += __shfl_xor_sync(FULLM, acc1.z, 1);
    acc1.w += __shfl_xor_sync(FULLM, acc1.w, 1);

    float xv[CPI];
    {
        float o0 = __shfl_xor_sync(FULLM, xc.x, 1);
        float o1 = __shfl_xor_sync(FULLM, xc.y, 1);
        float o2 = __shfl_xor_sync(FULLM, xc.z, 1);
        float o3 = __shfl_xor_sync(FULLM, xc.w, 1);
        int mine = 4 * p, theirs = 4 * (1 - p);
        xv[mine + 0] = xc.x; xv[mine + 1] = xc.y;
        xv[mine + 2] = xc.z; xv[mine + 3] = xc.w;
        xv[theirs + 0] = o0; xv[theirs + 1] = o1;
        xv[theirs + 2] = o2; xv[theirs + 3] = o3;
    }

    float cinv = 1.0f / (float)max(deg, 1);
    float av[CPI] = { acc0.x * cinv, acc0.y * cinv, acc0.z * cinv, acc0.w * cinv,
                      acc1.x * cinv, acc1.y * cinv, acc1.z * cinv, acc1.w * cinv };

    float outl[NCH];
    float ss = 0.0f;
#pragma unroll
    for (int k = 0; k < NCH; k++) {
        int c = p * NCH + k;
        float tt = s_bias[c];
#pragma unroll
        for (int i = 0; i < CI; i++) {
            tt = fmaf(av[i], s_wl[c * WS + i], tt);
            tt = fmaf(xv[i], s_wr[c * WS + i], tt);
        }
        outl[k] = tt;
        ss += tt * tt;
    }
    ss += __shfl_xor_sync(FULLM, ss, 1);
    float inv = 1.0f / fmaxf(sqrtf(ss), 1e-12f);
#pragma unroll
    for (int k = 0; k < NCH; k++)
        outl[k] = act ? fmaxf(outl[k] * inv, 0.0f) : 0.0f;

    if (act) {
        float4* yr = reinterpret_cast<float4*>(y) + (size_t)n * (CPO / 4) + p * (NCH / 4);
#pragma unroll
        for (int w = 0; w < NCH / 4; w++)
            yr[w] = make_float4(outl[4 * w], outl[4 * w + 1],
                                outl[4 * w + 2], outl[4 * w + 3]);
    }

    // BN stats for next layer
    float lsum[NCH], lsq[NCH];
#pragma unroll
    for (int k = 0; k < NCH; k++) { lsum[k] = outl[k]; lsq[k] = outl[k] * outl[k]; }
#pragma unroll
    for (int off = 2; off < 32; off <<= 1) {
#pragma unroll
        for (int k = 0; k < NCH; k++) {
            lsum[k] += __shfl_xor_sync(FULLM, lsum[k], off);
            lsq[k]  += __shfl_xor_sync(FULLM, lsq[k],  off);
        }
    }
    if ((threadIdx.x & 31) < 2) {
#pragma unroll
        for (int k = 0; k < NCH; k++) {
            int c = p * NCH + k;
            atomicAdd(&s_sum[c], lsum[k]);
            atomicAdd(&s_sq[c],  lsq[k]);
        }
    }
    __syncthreads();
    if (threadIdx.x < CO) {
        atomicAdd(&g_stats[SOUT + threadIdx.x], s_sum[threadIdx.x]);
        atomicAdd(&g_stats[SOUT + 32 + threadIdx.x], s_sq[threadIdx.x]);
    }
}

// ---------------- L4 kernel: 4 threads per node (edge-split, V=4) ------------
__global__ __launch_bounds__(256, 4)
void l4_kernel(const float4* __restrict__ x4,
               const float* __restrict__ wl,
               const float* __restrict__ bl,
               const float* __restrict__ wr,
               const float* __restrict__ bn_g,
               const float* __restrict__ bn_b,
               float* __restrict__ y) {
    constexpr int CI = 16, CO = 32, V = 4, WS = CI + 1;
    __shared__ float s_wl[CO * WS];
    __shared__ float s_wr[CO * WS];
    __shared__ float s_bias[CO];
    __shared__ float s_sc[CI], s_sh[CI];

    if (threadIdx.x < CI) {
        int c = threadIdx.x;
        float m  = g_stats[128 + c] * (1.0f / NN);
        float v  = g_stats[128 + 32 + c] * (1.0f / NN) - m * m;
        float sc = bn_g[c] * rsqrtf(v + 1e-5f);
        s_sc[c] = sc;
        s_sh[c] = bn_b[c] - m * sc;
    }
    __syncthreads();
    for (int i = threadIdx.x; i < CO * CI; i += blockDim.x) {
        int co = i / CI, ci = i % CI;
        float sc = s_sc[ci];
        s_wl[co * WS + ci] = wl[i] * sc;
        s_wr[co * WS + ci] = wr[i] * sc;
    }
    if (threadIdx.x < CO) {
        int co = threadIdx.x;
        float b = bl[co];
#pragma unroll
        for (int i = 0; i < CI; i++)
            b += s_sh[i] * (wl[co * CI + i] + wr[co * CI + i]);
        s_bias[co] = b;
    }
    __syncthreads();

    int t = blockIdx.x * blockDim.x + threadIdx.x;
    int n = t >> 2;                  // node (natural order)
    int p = t & 3;                   // quarter (edge slice / channel slice)
    int lane = threadIdx.x & 31;
    int base = lane & ~3;            // first lane of this node-group
    bool act = (n < NN);

    // self chunk p (coalesced)
    float4 xc = make_float4(0.f, 0.f, 0.f, 0.f);
    int deg = 0;
    if (act) {
        deg = min(g_cnt[n], CAP);
        xc = x4[(size_t)n * V + p];
    }

    // edge loop: lane p handles edges j = p, p+4, ... (full-row loads)
    float4 acc[V];
#pragma unroll
    for (int v = 0; v < V; v++) acc[v] = make_float4(0.f, 0.f, 0.f, 0.f);
    for (int j = p; j < deg; j += 4) {
        int s0 = g_slot[j * NN + n];
        const float4* r0 = x4 + (size_t)s0 * V;
        float4 a0 = r0[0], a1 = r0[1], a2 = r0[2], a3 = r0[3];
        acc[0].x += a0.x; acc[0].y += a0.y; acc[0].z += a0.z; acc[0].w += a0.w;
        acc[1].x += a1.x; acc[1].y += a1.y; acc[1].z += a1.z; acc[1].w += a1.w;
        acc[2].x += a2.x; acc[2].y += a2.y; acc[2].z += a2.z; acc[2].w += a2.w;
        acc[3].x += a3.x; acc[3].y += a3.y; acc[3].z += a3.z; acc[3].w += a3.w;
    }

    // merge acc across the 4-lane group (xor 1, 2)
#pragma unroll
    for (int off = 1; off < 4; off <<= 1) {
#pragma unroll
        for (int v = 0; v < V; v++) {
            acc[v].x += __shfl_xor_sync(FULLM, acc[v].x, off);
            acc[v].y += __shfl_xor_sync(FULLM, acc[v].y, off);
            acc[v].z += __shfl_xor_sync(FULLM, acc[v].z, off);
            acc[v].w += __shfl_xor_sync(FULLM, acc[v].w, off);
        }
    }

    // scale acc -> mean (in place), assemble self row via broadcasts
    float cinv = 1.0f / (float)max(deg, 1);
    float av[CI];
    {
        const float* ap = reinterpret_cast<const float*>(acc);
#pragma unroll
        for (int i = 0; i < CI; i++) av[i] = ap[i] * cinv;
    }
    float xv[CI];
#pragma unroll
    for (int c = 0; c < V; c++) {
        xv[4 * c + 0] = __shfl_sync(FULLM, xc.x, base + c);
        xv[4 * c + 1] = __shfl_sync(FULLM, xc.y, base + c);
        xv[4 * c + 2] = __shfl_sync(FULLM, xc.z, base + c);
        xv[4 * c + 3] = __shfl_sync(FULLM, xc.w, base + c);
    }

    // epilogue: lane p computes channels c = 8p .. 8p+7
    float outl[8];
    float ss = 0.0f;
#pragma unroll
    for (int k = 0; k < 8; k++) {
        int c = 8 * p + k;
        float tt = s_bias[c];
#pragma unroll
        for (int i = 0; i < CI; i++) {
            tt = fmaf(av[i], s_wl[c * WS + i], tt);
            tt = fmaf(xv[i], s_wr[c * WS + i], tt);
        }
        outl[k] = tt;
        ss += tt * tt;
    }
    ss += __shfl_xor_sync(FULLM, ss, 1);
    ss += __shfl_xor_sync(FULLM, ss, 2);
    float inv = 1.0f / fmaxf(sqrtf(ss), 1e-12f);

    if (act) {
        float4* yr = reinterpret_cast<float4*>(y) + (size_t)n * 8 + 2 * p;
#pragma unroll
        for (int w = 0; w < 2; w++) {
            float4 o;
            o.x = fmaxf(outl[4 * w + 0] * inv, 0.0f);
            o.y = fmaxf(outl[4 * w + 1] * inv, 0.0f);
            o.z = fmaxf(outl[4 * w + 2] * inv, 0.0f);
            o.w = fmaxf(outl[4 * w + 3] * inv, 0.0f);
            yr[w] = o;
        }
    }
}

// ---------------- launch ----------------------------------------------------
extern "C" void kernel_launch(void* const* d_in, const int* in_sizes, int n_in,
                              void* d_out, int out_size) {
    const float* x   = (const float*)d_in[0];
    const int*   ei  = (const int*)d_in[1];     // int32 edge_index (JAX x64 off)
    const float* w1l = (const float*)d_in[2];
    const float* b1l = (const float*)d_in[3];
    const float* w1r = (const float*)d_in[4];
    const float* w2l = (const float*)d_in[5];
    const float* b2l = (const float*)d_in[6];
    const float* w2r = (const float*)d_in[7];
    const float* w3l = (const float*)d_in[8];
    const float* b3l = (const float*)d_in[9];
    const float* w3r = (const float*)d_in[10];
    const float* w4l = (const float*)d_in[11];
    const float* b4l = (const float*)d_in[12];
    const float* w4r = (const float*)d_in[13];
    const float* g1  = (const float*)d_in[14];
    const float* be1 = (const float*)d_in[15];
    const float* g2  = (const float*)d_in[16];
    const float* be2 = (const float*)d_in[17];
    const float* g3  = (const float*)d_in[18];
    const float* be3 = (const float*)d_in[19];
    float* out = (float*)d_out;

    void *p_cnt, *p_stats, *p_bufA, *p_bufB;
    cudaGetSymbolAddress(&p_cnt, g_cnt);
    cudaGetSymbolAddress(&p_stats, g_stats);
    cudaGetSymbolAddress(&p_bufA, g_bufA4);
    cudaGetSymbolAddress(&p_bufB, g_bufB4);
    float* bufA = (float*)p_bufA;
    float* bufB = (float*)p_bufB;

    const int TB = 256;
    const int gridE  = (EE + TB - 1) / TB;
    const int gridN  = (NN + TB - 1) / TB;
    const int gridN2 = (2 * NN + TB - 1) / TB;
    const int gridN4 = (4 * NN + TB - 1) / TB;

    // bucket build (single pass)
    cudaMemsetAsync(p_cnt, 0, NN * sizeof(int));
    cudaMemsetAsync(p_stats, 0, 192 * sizeof(float));
    k_fill<<<gridE, TB>>>(ei);

    // L1: 4 -> 6 (pad 8), thread-per-node
    l1_kernel<<<gridN, TB>>>((const float4*)x, w1l, b1l, w1r, bufA);

    // L2: 6 (pad 8) -> 8, BN1 folded, 2 threads/node (reg-capped)
    split2_kernel<6, 8, 0, 64>
        <<<gridN2, TB>>>((const float4*)bufA, w2l, b2l, w2r, g1, be1, bufB);

    // L3: 8 -> 16, BN2 folded, 2 threads/node (reg-capped)
    split2_kernel<8, 16, 64, 128>
        <<<gridN2, TB>>>((const float4*)bufB, w3l, b3l, w3r, g2, be2, bufA);

    // L4: 16 -> 32, BN3 folded, 4 threads/node, straight to d_out
    l4_kernel<<<gridN4, TB>>>((const float4*)bufA, w4l, b4l, w4r, g3, be3, out);
}

// round 16
// speedup vs baseline: 1.5959x; 1.1358x over previous
#include <cuda_runtime.h>

#define NN 100000
#define EE 1600000
#define CAP 64   // max in-degree bucket capacity (Poisson(16): P(exceed) ~ 1e-19)
#define FULLM 0xffffffffu

// ---------------- scratch ---------------------------------------------------
__device__ int    g_cnt[NN];           // in-degree
__device__ int    g_slot[CAP * NN];    // src ids: slot[j*NN + dst], j < cnt[dst]
__device__ float4 g_bufA4[NN * 4];     // ping (max padded C = 16)
__device__ float4 g_bufB4[NN * 4];     // pong
__device__ float  g_stats[192];        // 3 layers x (32 sum + 32 sumsq)

// ---------------- bucket fill: 2 edges/thread, vectorized ------------------
__global__ void k_fill(const int* __restrict__ ei) {
    int e = (blockIdx.x * blockDim.x + threadIdx.x) * 2;
    if (e >= EE) return;
    int2 s = *reinterpret_cast<const int2*>(ei + e);
    int2 d = *reinterpret_cast<const int2*>(ei + EE + e);
    int p0 = atomicAdd(&g_cnt[d.x], 1);
    if (p0 < CAP) g_slot[p0 * NN + d.x] = s.x;
    int p1 = atomicAdd(&g_cnt[d.y], 1);
    if (p1 < CAP) g_slot[p1 * NN + d.y] = s.y;
}

// ---------------- L1 kernel (thread-per-node; V=1; 4-edge unroll) ------------
__global__ void l1_kernel(const float4* __restrict__ x4,
                          const float* __restrict__ wl,
                          const float* __restrict__ bl,
                          const float* __restrict__ wr,
                          float* __restrict__ y) {
    constexpr int CI = 4, CO = 6;
    __shared__ float s_wl[CO * CI];
    __shared__ float s_wr[CO * CI];
    __shared__ float s_bias[CO];
    __shared__ float s_sum[CO];
    __shared__ float s_sq[CO];
    for (int i = threadIdx.x; i < CO * CI; i += blockDim.x) {
        s_wl[i] = wl[i];
        s_wr[i] = wr[i];
    }
    if (threadIdx.x < CO) {
        s_bias[threadIdx.x] = bl[threadIdx.x];
        s_sum[threadIdx.x] = 0.0f;
        s_sq[threadIdx.x] = 0.0f;
    }
    __syncthreads();

    int n = blockIdx.x * blockDim.x + threadIdx.x;
    bool act = (n < NN);

    float out[CO];
#pragma unroll
    for (int c = 0; c < CO; c++) out[c] = 0.0f;

    if (act) {
        float4 xv4 = x4[n];
        float4 acc = make_float4(0.f, 0.f, 0.f, 0.f);
        float4 acc2 = make_float4(0.f, 0.f, 0.f, 0.f);
        int deg = min(g_cnt[n], CAP);
        int j = 0;
        for (; j + 4 <= deg; j += 4) {
            int s0 = g_slot[(j + 0) * NN + n];
            int s1 = g_slot[(j + 1) * NN + n];
            int s2 = g_slot[(j + 2) * NN + n];
            int s3 = g_slot[(j + 3) * NN + n];
            float4 a0 = x4[s0];
            float4 a1 = x4[s1];
            float4 a2 = x4[s2];
            float4 a3 = x4[s3];
            acc.x  += a0.x + a1.x; acc.y  += a0.y + a1.y;
            acc.z  += a0.z + a1.z; acc.w  += a0.w + a1.w;
            acc2.x += a2.x + a3.x; acc2.y += a2.y + a3.y;
            acc2.z += a2.z + a3.z; acc2.w += a2.w + a3.w;
        }
        for (; j < deg; j++) {
            int s0 = g_slot[j * NN + n];
            float4 a0 = x4[s0];
            acc.x += a0.x; acc.y += a0.y; acc.z += a0.z; acc.w += a0.w;
        }
        acc.x += acc2.x; acc.y += acc2.y; acc.z += acc2.z; acc.w += acc2.w;

        float cinv = 1.0f / (float)max(deg, 1);
        float av[CI] = { acc.x * cinv, acc.y * cinv, acc.z * cinv, acc.w * cinv };
        float xv[CI] = { xv4.x, xv4.y, xv4.z, xv4.w };

        float ss = 0.0f;
#pragma unroll
        for (int co = 0; co < CO; co++) {
            float t = s_bias[co];
#pragma unroll
            for (int i = 0; i < CI; i++) {
                t = fmaf(av[i], s_wl[co * CI + i], t);
                t = fmaf(xv[i], s_wr[co * CI + i], t);
            }
            out[co] = t;
            ss += t * t;
        }
        float inv = 1.0f / fmaxf(sqrtf(ss), 1e-12f);
#pragma unroll
        for (int co = 0; co < CO; co++)
            out[co] = fmaxf(out[co] * inv, 0.0f);

        float4* yr4 = reinterpret_cast<float4*>(y) + (size_t)n * 2;
        yr4[0] = make_float4(out[0], out[1], out[2], out[3]);
        yr4[1] = make_float4(out[4], out[5], 0.0f, 0.0f);
    }

#pragma unroll
    for (int c = 0; c < CO; c++) {
        float v = out[c];
        float q = v * v;
#pragma unroll
        for (int off = 16; off; off >>= 1) {
            v += __shfl_xor_sync(FULLM, v, off);
            q += __shfl_xor_sync(FULLM, q, off);
        }
        if ((threadIdx.x & 31) == 0) {
            atomicAdd(&s_sum[c], v);
            atomicAdd(&s_sq[c], q);
        }
    }
    __syncthreads();
    if (threadIdx.x < CO) {
        atomicAdd(&g_stats[0 + threadIdx.x], s_sum[threadIdx.x]);
        atomicAdd(&g_stats[32 + threadIdx.x], s_sq[threadIdx.x]);
    }
}

// ---------------- fused layer (R12-proven thread-per-node; L2, L3) -----------
template <int CI, int CO, int CPI, int CPO, int SIN, int SOUT>
__global__ void node_kernel(const float4* __restrict__ x4,
                            const float* __restrict__ wl,
                            const float* __restrict__ bl,
                            const float* __restrict__ wr,
                            const float* __restrict__ bn_g,
                            const float* __restrict__ bn_b,
                            float* __restrict__ y) {
    constexpr int V = CPI / 4;
    constexpr int W = CPO / 4;
    __shared__ float s_wl[CO * CI];
    __shared__ float s_wr[CO * CI];
    __shared__ float s_bias[CO];
    __shared__ float s_sc[CI], s_sh[CI];
    __shared__ float s_sum[CO];
    __shared__ float s_sq[CO];

    if (threadIdx.x < CI) {
        int c = threadIdx.x;
        float m  = g_stats[SIN + c] * (1.0f / NN);
        float v  = g_stats[SIN + 32 + c] * (1.0f / NN) - m * m;
        float sc = bn_g[c] * rsqrtf(v + 1e-5f);
        s_sc[c] = sc;
        s_sh[c] = bn_b[c] - m * sc;
    }
    __syncthreads();
    for (int i = threadIdx.x; i < CO * CI; i += blockDim.x) {
        float sc = s_sc[i % CI];
        s_wl[i] = wl[i] * sc;
        s_wr[i] = wr[i] * sc;
    }
    if (threadIdx.x < CO) {
        int co = threadIdx.x;
        float b = bl[co];
#pragma unroll
        for (int i = 0; i < CI; i++)
            b += s_sh[i] * (wl[co * CI + i] + wr[co * CI + i]);
        s_bias[co] = b;
        s_sum[co] = 0.0f;
        s_sq[co] = 0.0f;
    }
    __syncthreads();

    int n = blockIdx.x * blockDim.x + threadIdx.x;
    bool act = (n < NN);

    float out[CO];
#pragma unroll
    for (int c = 0; c < CO; c++) out[c] = 0.0f;

    if (act) {
        float4 xv4[V];
        const float4* xr = x4 + (size_t)n * V;
#pragma unroll
        for (int v = 0; v < V; v++) xv4[v] = xr[v];

        float4 acc[V];
#pragma unroll
        for (int v = 0; v < V; v++) acc[v] = make_float4(0.f, 0.f, 0.f, 0.f);

        int deg = min(g_cnt[n], CAP);
        int j = 0;
        for (; j + 1 < deg; j += 2) {
            int s0 = g_slot[j * NN + n];
            int s1 = g_slot[(j + 1) * NN + n];
            const float4* r0 = x4 + (size_t)s0 * V;
            const float4* r1 = x4 + (size_t)s1 * V;
            float4 a0[V], a1[V];
#pragma unroll
            for (int v = 0; v < V; v++) { a0[v] = r0[v]; a1[v] = r1[v]; }
#pragma unroll
            for (int v = 0; v < V; v++) {
                acc[v].x += a0[v].x + a1[v].x;
                acc[v].y += a0[v].y + a1[v].y;
                acc[v].z += a0[v].z + a1[v].z;
                acc[v].w += a0[v].w + a1[v].w;
            }
        }
        if (j < deg) {
            int s0 = g_slot[j * NN + n];
            const float4* r0 = x4 + (size_t)s0 * V;
#pragma unroll
            for (int v = 0; v < V; v++) {
                float4 a0 = r0[v];
                acc[v].x += a0.x; acc[v].y += a0.y;
                acc[v].z += a0.z; acc[v].w += a0.w;
            }
        }

        float cinv = 1.0f / (float)max(deg, 1);
        float av[CI], xv[CI];
        const float* ap = reinterpret_cast<const float*>(acc);
        const float* xp = reinterpret_cast<const float*>(xv4);
#pragma unroll
        for (int i = 0; i < CI; i++) { av[i] = ap[i] * cinv; xv[i] = xp[i]; }

        float ss = 0.0f;
#pragma unroll
        for (int co = 0; co < CO; co++) {
            float t = s_bias[co];
#pragma unroll
            for (int i = 0; i < CI; i++) {
                t = fmaf(av[i], s_wl[co * CI + i], t);
                t = fmaf(xv[i], s_wr[co * CI + i], t);
            }
            out[co] = t;
            ss += t * t;
        }
        float inv = 1.0f / fmaxf(sqrtf(ss), 1e-12f);
#pragma unroll
        for (int co = 0; co < CO; co++)
            out[co] = fmaxf(out[co] * inv, 0.0f);   // L2 norm then relu

        float4* yr4 = reinterpret_cast<float4*>(y) + (size_t)n * W;
#pragma unroll
        for (int w = 0; w < W; w++) {
            float4 o;
            o.x = (4 * w + 0 < CO) ? out[4 * w + 0 < CO ? 4 * w + 0 : 0] : 0.0f;
            o.y = (4 * w + 1 < CO) ? out[4 * w + 1 < CO ? 4 * w + 1 : 0] : 0.0f;
            o.z = (4 * w + 2 < CO) ? out[4 * w + 2 < CO ? 4 * w + 2 : 0] : 0.0f;
            o.w = (4 * w + 3 < CO) ? out[4 * w + 3 < CO ? 4 * w + 3 : 0] : 0.0f;
            yr4[w] = o;
        }
    }

#pragma unroll
    for (int c = 0; c < CO; c++) {
        float v = out[c];
        float q = v * v;
#pragma unroll
        for (int off = 16; off; off >>= 1) {
            v += __shfl_xor_sync(FULLM, v, off);
            q += __shfl_xor_sync(FULLM, q, off);
        }
        if ((threadIdx.x & 31) == 0) {
            atomicAdd(&s_sum[c], v);
            atomicAdd(&s_sq[c], q);
        }
    }
    __syncthreads();
    if (threadIdx.x < CO) {
        atomicAdd(&g_stats[SOUT + threadIdx.x], s_sum[threadIdx.x]);
        atomicAdd(&g_stats[SOUT + 32 + threadIdx.x], s_sq[threadIdx.x]);
    }
}

// ---------------- L4 kernel: 2 threads per node (edge-split, V=4) ------------
__global__ void l4_kernel(const float4* __restrict__ x4,
                          const float* __restrict__ wl,
                          const float* __restrict__ bl,
                          const float* __restrict__ wr,
                          const float* __restrict__ bn_g,
                          const float* __restrict__ bn_b,
                          float* __restrict__ y) {
    constexpr int CI = 16, CO = 32, V = 4, WS = CI + 1;
    __shared__ float s_wl[CO * WS];
    __shared__ float s_wr[CO * WS];
    __shared__ float s_bias[CO];
    __shared__ float s_sc[CI], s_sh[CI];

    if (threadIdx.x < CI) {
        int c = threadIdx.x;
        float m  = g_stats[128 + c] * (1.0f / NN);
        float v  = g_stats[128 + 32 + c] * (1.0f / NN) - m * m;
        float sc = bn_g[c] * rsqrtf(v + 1e-5f);
        s_sc[c] = sc;
        s_sh[c] = bn_b[c] - m * sc;
    }
    __syncthreads();
    for (int i = threadIdx.x; i < CO * CI; i += blockDim.x) {
        int co = i / CI, ci = i % CI;
        float sc = s_sc[ci];
        s_wl[co * WS + ci] = wl[i] * sc;
        s_wr[co * WS + ci] = wr[i] * sc;
    }
    if (threadIdx.x < CO) {
        int co = threadIdx.x;
        float b = bl[co];
#pragma unroll
        for (int i = 0; i < CI; i++)
            b += s_sh[i] * (wl[co * CI + i] + wr[co * CI + i]);
        s_bias[co] = b;
    }
    __syncthreads();

    int t = blockIdx.x * blockDim.x + threadIdx.x;
    int n = t >> 1;
    int p = t & 1;
    bool act = (n < NN);

    float4 xc0 = make_float4(0.f, 0.f, 0.f, 0.f);
    float4 xc1 = make_float4(0.f, 0.f, 0.f, 0.f);
    int deg = 0;
    if (act) {
        deg = min(g_cnt[n], CAP);
        xc0 = x4[(size_t)n * V + 2 * p + 0];
        xc1 = x4[(size_t)n * V + 2 * p + 1];
    }

    float4 acc[V];
#pragma unroll
    for (int v = 0; v < V; v++) acc[v] = make_float4(0.f, 0.f, 0.f, 0.f);
    for (int j = p; j < deg; j += 2) {
        int s0 = g_slot[j * NN + n];
        const float4* r0 = x4 + (size_t)s0 * V;
        float4 a0 = r0[0], a1 = r0[1], a2 = r0[2], a3 = r0[3];
        acc[0].x += a0.x; acc[0].y += a0.y; acc[0].z += a0.z; acc[0].w += a0.w;
        acc[1].x += a1.x; acc[1].y += a1.y; acc[1].z += a1.z; acc[1].w += a1.w;
        acc[2].x += a2.x; acc[2].y += a2.y; acc[2].z += a2.z; acc[2].w += a2.w;
        acc[3].x += a3.x; acc[3].y += a3.y; acc[3].z += a3.z; acc[3].w += a3.w;
    }

#pragma unroll
    for (int v = 0; v < V; v++) {
        acc[v].x += __shfl_xor_sync(FULLM, acc[v].x, 1);
        acc[v].y += __shfl_xor_sync(FULLM, acc[v].y, 1);
        acc[v].z += __shfl_xor_sync(FULLM, acc[v].z, 1);
        acc[v].w += __shfl_xor_sync(FULLM, acc[v].w, 1);
    }
    float xv[CI];
    {
        float oth[8];
        oth[0] = __shfl_xor_sync(FULLM, xc0.x, 1);
        oth[1] = __shfl_xor_sync(FULLM, xc0.y, 1);
        oth[2] = __shfl_xor_sync(FULLM, xc0.z, 1);
        oth[3] = __shfl_xor_sync(FULLM, xc0.w, 1);
        oth[4] = __shfl_xor_sync(FULLM, xc1.x, 1);
        oth[5] = __shfl_xor_sync(FULLM, xc1.y, 1);
        oth[6] = __shfl_xor_sync(FULLM, xc1.z, 1);
        oth[7] = __shfl_xor_sync(FULLM, xc1.w, 1);
        int mine = 8 * p, theirs = 8 * (1 - p);
        xv[mine + 0] = xc0.x; xv[mine + 1] = xc0.y;
        xv[mine + 2] = xc0.z; xv[mine + 3] = xc0.w;
        xv[mine + 4] = xc1.x; xv[mine + 5] = xc1.y;
        xv[mine + 6] = xc1.z; xv[mine + 7] = xc1.w;
#pragma unroll
        for (int k = 0; k < 8; k++) xv[theirs + k] = oth[k];
    }

    float cinv = 1.0f / (float)max(deg, 1);
    float av[CI];
    {
        const float* ap = reinterpret_cast<const float*>(acc);
#pragma unroll
        for (int i = 0; i < CI; i++) av[i] = ap[i] * cinv;
    }

    float outl[16];
    float ss = 0.0f;
#pragma unroll
    for (int k = 0; k < 16; k++) {
        int c = 16 * p + k;
        float tt = s_bias[c];
#pragma unroll
        for (int i = 0; i < CI; i++) {
            tt = fmaf(av[i], s_wl[c * WS + i], tt);
            tt = fmaf(xv[i], s_wr[c * WS + i], tt);
        }
        outl[k] = tt;
        ss += tt * tt;
    }
    ss += __shfl_xor_sync(FULLM, ss, 1);
    float inv = 1.0f / fmaxf(sqrtf(ss), 1e-12f);

    if (act) {
        float4* yr = reinterpret_cast<float4*>(y) + (size_t)n * 8 + 4 * p;
#pragma unroll
        for (int w = 0; w < 4; w++) {
            float4 o;
            o.x = fmaxf(outl[4 * w + 0] * inv, 0.0f);
            o.y = fmaxf(outl[4 * w + 1] * inv, 0.0f);
            o.z = fmaxf(outl[4 * w + 2] * inv, 0.0f);
            o.w = fmaxf(outl[4 * w + 3] * inv, 0.0f);
            yr[w] = o;
        }
    }
}

// ---------------- launch ----------------------------------------------------
extern "C" void kernel_launch(void* const* d_in, const int* in_sizes, int n_in,
                              void* d_out, int out_size) {
    const float* x   = (const float*)d_in[0];
    const int*   ei  = (const int*)d_in[1];     // int32 edge_index (JAX x64 off)
    const float* w1l = (const float*)d_in[2];
    const float* b1l = (const float*)d_in[3];
    const float* w1r = (const float*)d_in[4];
    const float* w2l = (const float*)d_in[5];
    const float* b2l = (const float*)d_in[6];
    const float* w2r = (const float*)d_in[7];
    const float* w3l = (const float*)d_in[8];
    const float* b3l = (const float*)d_in[9];
    const float* w3r = (const float*)d_in[10];
    const float* w4l = (const float*)d_in[11];
    const float* b4l = (const float*)d_in[12];
    const float* w4r = (const float*)d_in[13];
    const float* g1  = (const float*)d_in[14];
    const float* be1 = (const float*)d_in[15];
    const float* g2  = (const float*)d_in[16];
    const float* be2 = (const float*)d_in[17];
    const float* g3  = (const float*)d_in[18];
    const float* be3 = (const float*)d_in[19];
    float* out = (float*)d_out;

    void *p_cnt, *p_stats, *p_bufA, *p_bufB;
    cudaGetSymbolAddress(&p_cnt, g_cnt);
    cudaGetSymbolAddress(&p_stats, g_stats);
    cudaGetSymbolAddress(&p_bufA, g_bufA4);
    cudaGetSymbolAddress(&p_bufB, g_bufB4);
    float* bufA = (float*)p_bufA;
    float* bufB = (float*)p_bufB;

    const int TB = 256;
    const int gridE2 = (EE / 2 + TB - 1) / TB;
    const int gridN  = (NN + TB - 1) / TB;
    const int gridN2 = (2 * NN + TB - 1) / TB;

    // bucket build (single pass, 2 edges/thread)
    cudaMemsetAsync(p_cnt, 0, NN * sizeof(int));
    cudaMemsetAsync(p_stats, 0, 192 * sizeof(float));
    k_fill<<<gridE2, TB>>>(ei);

    // L1: 4 -> 6 (pad 8), thread-per-node, 4-edge unroll
    l1_kernel<<<gridN, TB>>>((const float4*)x, w1l, b1l, w1r, bufA);

    // L2: 6 (pad 8) -> 8, BN1 folded
    node_kernel<6, 8, 8, 8, 0, 64>
        <<<gridN, TB>>>((const float4*)bufA, w2l, b2l, w2r, g1, be1, bufB);

    // L3: 8 -> 16, BN2 folded
    node_kernel<8, 16, 8, 16, 64, 128>
        <<<gridN, TB>>>((const float4*)bufB, w3l, b3l, w3r, g2, be2, bufA);

    // L4: 16 -> 32, BN3 folded, 2 threads/node edge-split, straight to d_out
    l4_kernel<<<gridN2, TB>>>((const float4*)bufA, w4l, b4l, w4r, g3, be3, out);
}